// round 9
// baseline (speedup 1.0000x reference)
#include <cuda_runtime.h>
#include <math.h>

// ---------------------------------------------------------------------------
// Problem constants (fixed by setup_inputs)
// ---------------------------------------------------------------------------
#define Bn 64
#define Ln 512
#define Hn 256
#define H3 768
#define An 128
#define NDEPTH 4
#define NROWS (Ln * Bn)          /* 32768, t-major: row = t*Bn + b */
#define XPW 896                  /* 768 (gru proj) + 128 (action proj) */
#define OUT_ACT 16384            /* Bn*Hn */
#define OUT_POL 147456           /* OUT_ACT + Bn*NDEPTH*Ln */

// ---------------------------------------------------------------------------
// Static scratch (device-global arrays: allowed; no cudaMalloc anywhere)
// ---------------------------------------------------------------------------
__device__ float g_hseq[NROWS * Hn];                 // 32 MB
__device__ float g_xpz[(size_t)NROWS * XPW];         // 112 MB
__device__ float g_wpack[256 * XPW];                 // [W | W_action_1]
__device__ float g_upack[256 * XPW];                 // [U | U_action_1]
__device__ unsigned char g_mask[NROWS];

// ---------------------------------------------------------------------------
// Pack [M(256x768) | A(256x128)] -> dst(256x896). which: 0 -> g_wpack, 1 -> g_upack
// ---------------------------------------------------------------------------
__global__ void pack_k(const float* __restrict__ Wm,
                       const float* __restrict__ Wa, int which)
{
    int i = blockIdx.x * blockDim.x + threadIdx.x;
    if (i < 256 * XPW) {
        int k = i / XPW, c = i % XPW;
        float v = (c < H3) ? Wm[k * H3 + c] : Wa[k * An + (c - H3)];
        if (which) g_upack[i] = v; else g_wpack[i] = v;
    }
}

// mask input is (B, L) 4-byte scalars (int32 or f32 0/1; nonzero test works for both)
__global__ void initmask_k(const int* __restrict__ m)
{
    int i = blockIdx.x * blockDim.x + threadIdx.x;
    if (i < NROWS) {
        int t = i >> 6, b = i & 63;
        g_mask[i] = (m[b * Ln + t] != 0) ? 1 : 0;
    }
}

// ---------------------------------------------------------------------------
// GEMM: C[32768 x N] = A[32768 x 256] @ B[256 x N] (+ bias)
// mode 0: A = x with row permutation (b-major -> t-major), B = W_emb, C = g_hseq
// mode 1: A = g_hseq, B = g_wpack, C = g_xpz
// BM=128, BN=128, BK=16, 256 threads, 8x8 microtile. All dims divide exactly.
// ---------------------------------------------------------------------------
__global__ void __launch_bounds__(256) gemm_k(
    const float* __restrict__ Aex, const float* __restrict__ Bex,
    const float* __restrict__ bias, int N, int mode)
{
    const float* __restrict__ A = mode ? g_hseq : Aex;
    const float* __restrict__ B = mode ? g_wpack : Bex;
    float* __restrict__ C       = mode ? g_xpz  : g_hseq;
    const int permute = (mode == 0);

    __shared__ __align__(16) float As[16][132];   // 132*4 = 528 = 33*16 (aligned rows)
    __shared__ __align__(16) float Bs[16][128];

    const int tid = threadIdx.x;
    const int bx = blockIdx.x, by = blockIdx.y;
    const int tx = tid & 15, ty = tid >> 4;

    float acc[8][8];
#pragma unroll
    for (int i = 0; i < 8; i++)
#pragma unroll
        for (int j = 0; j < 8; j++) acc[i][j] = 0.0f;

    const int ar  = tid & 127;            // A row within tile
    const int akh = (tid >> 7) * 8;       // A k-offset (0 or 8)
    const int brow = tid >> 4;            // B k row (0..15)
    const int bcol = (tid & 15) * 8;      // B col group

    for (int kt = 0; kt < 256; kt += 16) {
        int m = by * 128 + ar;
        long arow = permute ? ((long)(m & 63) * Ln + (m >> 6)) : (long)m;
        const float* ap = A + arow * 256 + kt + akh;
        float4 a0 = *(const float4*)ap;
        float4 a1 = *(const float4*)(ap + 4);
        As[akh + 0][ar] = a0.x; As[akh + 1][ar] = a0.y;
        As[akh + 2][ar] = a0.z; As[akh + 3][ar] = a0.w;
        As[akh + 4][ar] = a1.x; As[akh + 5][ar] = a1.y;
        As[akh + 6][ar] = a1.z; As[akh + 7][ar] = a1.w;

        const float* bp = B + (long)(kt + brow) * N + bx * 128 + bcol;
        *(float4*)&Bs[brow][bcol]     = *(const float4*)bp;
        *(float4*)&Bs[brow][bcol + 4] = *(const float4*)(bp + 4);
        __syncthreads();

#pragma unroll
        for (int kk = 0; kk < 16; kk++) {
            float a8[8], b8[8];
            *(float4*)&a8[0] = *(const float4*)&As[kk][ty * 8];
            *(float4*)&a8[4] = *(const float4*)&As[kk][ty * 8 + 4];
            *(float4*)&b8[0] = *(const float4*)&Bs[kk][tx * 8];
            *(float4*)&b8[4] = *(const float4*)&Bs[kk][tx * 8 + 4];
#pragma unroll
            for (int i = 0; i < 8; i++)
#pragma unroll
                for (int j = 0; j < 8; j++)
                    acc[i][j] = fmaf(a8[i], b8[j], acc[i][j]);
        }
        __syncthreads();
    }

    float bv[8];
#pragma unroll
    for (int j = 0; j < 8; j++)
        bv[j] = bias ? bias[bx * 128 + tx * 8 + j] : 0.0f;

#pragma unroll
    for (int i = 0; i < 8; i++) {
        long row = by * 128 + ty * 8 + i;
        float* cp = C + row * N + bx * 128 + tx * 8;
        float4 o0, o1;
        o0.x = acc[i][0] + bv[0]; o0.y = acc[i][1] + bv[1];
        o0.z = acc[i][2] + bv[2]; o0.w = acc[i][3] + bv[3];
        o1.x = acc[i][4] + bv[4]; o1.y = acc[i][5] + bv[5];
        o1.z = acc[i][6] + bv[6]; o1.w = acc[i][7] + bv[7];
        *(float4*)cp       = o0;
        *(float4*)(cp + 4) = o1;
    }
}

// ---------------------------------------------------------------------------
// Row LayerNorm of g_xpz[:, 0:768] in place (gamma0/beta0). 1 block/row.
// ---------------------------------------------------------------------------
__global__ void __launch_bounds__(256) lnx_k(const float* __restrict__ gam,
                                             const float* __restrict__ bet)
{
    long row = blockIdx.x;
    float* p = g_xpz + row * XPW;
    int tid = threadIdx.x;
    float v0 = p[tid], v1 = p[tid + 256], v2 = p[tid + 512];
    float s = v0 + v1 + v2;
    float q = v0 * v0 + v1 * v1 + v2 * v2;

    __shared__ float rs[8], rq[8], st[2];
#pragma unroll
    for (int off = 16; off; off >>= 1) {
        s += __shfl_down_sync(0xffffffffu, s, off);
        q += __shfl_down_sync(0xffffffffu, q, off);
    }
    if ((tid & 31) == 0) { rs[tid >> 5] = s; rq[tid >> 5] = q; }
    __syncthreads();
    if (tid == 0) {
        float S = 0.f, Q = 0.f;
#pragma unroll
        for (int i = 0; i < 8; i++) { S += rs[i]; Q += rq[i]; }
        float mean = S * (1.0f / 768.0f);
        float var  = Q * (1.0f / 768.0f) - mean * mean;
        st[0] = mean;
        st[1] = rsqrtf(var + 1e-5f);
    }
    __syncthreads();
    float mean = st[0], r = st[1];
    p[tid]       = (v0 - mean) * r * gam[tid]       + bet[tid];
    p[tid + 256] = (v1 - mean) * r * gam[tid + 256] + bet[tid + 256];
    p[tid + 512] = (v2 - mean) * r * gam[tid + 512] + bet[tid + 512];
}

// ---------------------------------------------------------------------------
// Recurrent scan for one depth. 32 blocks x 256 threads; block owns batch
// rows b0=2*bx, b0+1 for all 512 steps. No inter-block sync needed.
// ---------------------------------------------------------------------------
__global__ void __launch_bounds__(256) scan_k(
    const float* __restrict__ bias3, const float* __restrict__ ba1,
    const float* __restrict__ wa2,   const float* __restrict__ ba2,
    const float* __restrict__ gam1,  const float* __restrict__ bet1,
    float* __restrict__ out, int out_size, int dep)
{
    __shared__ float2 hpair[Hn];           // (h_row0[k], h_row1[k])
    __shared__ float zb[2][XPW];           // h @ [U | Ua1] per row
    __shared__ float cb[H3], cg[H3], cbe[H3];
    __shared__ float cba1[An], cwa2[2 * An], cba2[2];
    __shared__ float red[32], ared[16], stats[4];
    __shared__ unsigned char msk[2][Ln];

    const int tid = threadIdx.x;
    const int b0 = blockIdx.x * 2;
    const int lane = tid & 31, wp = tid >> 5;

    for (int i = tid; i < H3; i += 256) {
        cb[i] = bias3[i]; cg[i] = gam1[i]; cbe[i] = bet1[i];
    }
    if (tid < An) {
        cba1[tid] = ba1[tid];
        cwa2[2 * tid] = wa2[2 * tid];
        cwa2[2 * tid + 1] = wa2[2 * tid + 1];
    }
    if (tid < 2) cba2[tid] = ba2[tid];
    hpair[tid] = make_float2(0.0f, 0.0f);   // h0 = zeros
    for (int i = tid; i < Ln; i += 256) {
        msk[0][i] = g_mask[i * Bn + b0];
        msk[1][i] = g_mask[i * Bn + b0 + 1];
    }
    __syncthreads();

    const int c4 = tid * 4;

    for (int t = 0; t < Ln; t++) {
        const int m0 = msk[0][t], m1 = msk[1][t];   // read BEFORE updates
        const long base0 = (long)(t * Bn + b0) * XPW;
        const long base1 = base0 + XPW;

        // ---- z = h @ [U | Ua1] for both rows (threads 0..223 cover 896 cols)
        if (tid < 224) {
            float a0x = 0.f, a0y = 0.f, a0z = 0.f, a0w = 0.f;
            float a1x = 0.f, a1y = 0.f, a1z = 0.f, a1w = 0.f;
#pragma unroll 4
            for (int k = 0; k < Hn; k++) {
                float4 u = *(const float4*)&g_upack[k * XPW + c4];
                float2 h2 = hpair[k];
                a0x = fmaf(h2.x, u.x, a0x); a0y = fmaf(h2.x, u.y, a0y);
                a0z = fmaf(h2.x, u.z, a0z); a0w = fmaf(h2.x, u.w, a0w);
                a1x = fmaf(h2.y, u.x, a1x); a1y = fmaf(h2.y, u.y, a1y);
                a1z = fmaf(h2.y, u.z, a1z); a1w = fmaf(h2.y, u.w, a1w);
            }
            zb[0][c4] = a0x; zb[0][c4 + 1] = a0y; zb[0][c4 + 2] = a0z; zb[0][c4 + 3] = a0w;
            zb[1][c4] = a1x; zb[1][c4 + 1] = a1y; zb[1][c4 + 2] = a1z; zb[1][c4 + 3] = a1w;
        }
        __syncthreads();

        // ---- LN partial sums (768 cols, both rows) + action partial dot
        {
            float x0 = zb[0][tid], x1 = zb[0][tid + 256], x2 = zb[0][tid + 512];
            float y0 = zb[1][tid], y1 = zb[1][tid + 256], y2 = zb[1][tid + 512];
            float s0 = x0 + x1 + x2, q0 = x0 * x0 + x1 * x1 + x2 * x2;
            float s1 = y0 + y1 + y2, q1 = y0 * y0 + y1 * y1 + y2 * y2;
#pragma unroll
            for (int off = 16; off; off >>= 1) {
                s0 += __shfl_down_sync(0xffffffffu, s0, off);
                q0 += __shfl_down_sync(0xffffffffu, q0, off);
                s1 += __shfl_down_sync(0xffffffffu, s1, off);
                q1 += __shfl_down_sync(0xffffffffu, q1, off);
            }
            if (lane == 0) {
                red[wp * 4 + 0] = s0; red[wp * 4 + 1] = q0;
                red[wp * 4 + 2] = s1; red[wp * 4 + 3] = q1;
            }
            // action: warps 0-3 -> row0, warps 4-7 -> row1
            int rr = tid >> 7, ac = tid & 127;
            long ab = rr ? base1 : base0;
            float xa = g_xpz[ab + H3 + ac];
            float ta = tanhf(xa + zb[rr][H3 + ac] + cba1[ac]);
            float p0 = ta * cwa2[2 * ac];
            float p1 = ta * cwa2[2 * ac + 1];
#pragma unroll
            for (int off = 16; off; off >>= 1) {
                p0 += __shfl_down_sync(0xffffffffu, p0, off);
                p1 += __shfl_down_sync(0xffffffffu, p1, off);
            }
            if (lane == 0) { ared[wp * 2] = p0; ared[wp * 2 + 1] = p1; }
        }
        __syncthreads();

        // ---- finalize stats (thread 0) + logits/policy/action (threads 0,128)
        if (tid == 0) {
            float S0 = 0.f, Q0 = 0.f, S1 = 0.f, Q1 = 0.f;
#pragma unroll
            for (int w = 0; w < 8; w++) {
                S0 += red[w * 4 + 0]; Q0 += red[w * 4 + 1];
                S1 += red[w * 4 + 2]; Q1 += red[w * 4 + 3];
            }
            float mean0 = S0 * (1.0f / 768.0f);
            float var0  = Q0 * (1.0f / 768.0f) - mean0 * mean0;
            float mean1 = S1 * (1.0f / 768.0f);
            float var1  = Q1 * (1.0f / 768.0f) - mean1 * mean1;
            stats[0] = mean0; stats[1] = rsqrtf(var0 + 1e-5f);
            stats[2] = mean1; stats[3] = rsqrtf(var1 + 1e-5f);
        }
        if ((tid & 127) == 0) {
            int r = tid >> 7;
            float l0 = cba2[0], l1 = cba2[1];
#pragma unroll
            for (int w = 0; w < 4; w++) {
                l0 += ared[(r * 4 + w) * 2];
                l1 += ared[(r * 4 + w) * 2 + 1];
            }
            float mx = fmaxf(l0, l1);
            float e0 = expf(l0 - mx), e1 = expf(l1 - mx);
            float inv = 1.0f / (e0 + e1);
            int m = r ? m1 : m0;
            int act = (l1 > l0) && m;      // pol1>pol0 <=> l1>l0 (softmax monotone)
            int b = b0 + r;
            int ai = OUT_ACT + (b * NDEPTH + dep) * Ln + t;
            if (ai < out_size) out[ai] = (float)act;
            int pi = OUT_POL + ((b * NDEPTH + dep) * Ln + t) * 2;
            if (pi + 1 < out_size) { out[pi] = e0 * inv; out[pi + 1] = e1 * inv; }
            unsigned char nm = (unsigned char)(m && act);
            msk[r][t] = nm;
            g_mask[t * Bn + b] = nm;
        }
        __syncthreads();

        // ---- gates + state update (each thread owns hidden column c = tid)
        {
            int c = tid;
            float mean0 = stats[0], rstd0 = stats[1];
            float mean1 = stats[2], rstd1 = stats[3];
            float g0 = cg[c], g1 = cg[c + 256], g2 = cg[c + 512];
            float e0 = cbe[c], e1 = cbe[c + 256], e2 = cbe[c + 512];
            float bb0 = cb[c], bb1 = cb[c + 256], bb2 = cb[c + 512];
            float2 hold = hpair[c];

            float hp0 = (zb[0][c]       - mean0) * rstd0 * g0 + e0;
            float hp1 = (zb[0][c + 256] - mean0) * rstd0 * g1 + e1;
            float hp2 = (zb[0][c + 512] - mean0) * rstd0 * g2 + e2;
            float xp0 = g_xpz[base0 + c];
            float xp1 = g_xpz[base0 + c + 256];
            float xp2 = g_xpz[base0 + c + 512];
            float rg = 1.0f / (1.0f + expf(-(xp0 + hp0 + bb0)));
            float zg = 1.0f / (1.0f + expf(-(xp1 + hp1 + bb1)));
            float hh = tanhf(xp2 + rg * hp2 + bb2);
            float hn = zg * hold.x + (1.0f - zg) * hh;
            float ho0 = m0 ? hn : hold.x;

            hp0 = (zb[1][c]       - mean1) * rstd1 * g0 + e0;
            hp1 = (zb[1][c + 256] - mean1) * rstd1 * g1 + e1;
            hp2 = (zb[1][c + 512] - mean1) * rstd1 * g2 + e2;
            xp0 = g_xpz[base1 + c];
            xp1 = g_xpz[base1 + c + 256];
            xp2 = g_xpz[base1 + c + 512];
            rg = 1.0f / (1.0f + expf(-(xp0 + hp0 + bb0)));
            zg = 1.0f / (1.0f + expf(-(xp1 + hp1 + bb1)));
            hh = tanhf(xp2 + rg * hp2 + bb2);
            hn = zg * hold.y + (1.0f - zg) * hh;
            float ho1 = m1 ? hn : hold.y;

            g_hseq[(long)(t * Bn + b0) * Hn + c]     = ho0;
            g_hseq[(long)(t * Bn + b0 + 1) * Hn + c] = ho1;
            hpair[c] = make_float2(ho0, ho1);
        }
        __syncthreads();
    }
}

// ---------------------------------------------------------------------------
// output = h_seq[-1] (t = 511), (B, H)
// ---------------------------------------------------------------------------
__global__ void copyout_k(float* __restrict__ out, int out_size)
{
    int i = blockIdx.x * blockDim.x + threadIdx.x;
    if (i < Bn * Hn && i < out_size)
        out[i] = g_hseq[(long)(511 * Bn + (i >> 8)) * Hn + (i & 255)];
}

// ---------------------------------------------------------------------------
// launch
// ---------------------------------------------------------------------------
extern "C" void kernel_launch(void* const* d_in, const int* in_sizes, int n_in,
                              void* d_out, int out_size)
{
    const float* x      = (const float*)d_in[0];
    const int*   maskp  = (const int*)  d_in[1];
    const float* W_emb  = (const float*)d_in[2];
    const float* b_emb  = (const float*)d_in[3];
    const float* W      = (const float*)d_in[4];
    const float* U      = (const float*)d_in[5];
    const float* b      = (const float*)d_in[6];
    const float* Wa1    = (const float*)d_in[7];
    const float* Ua1    = (const float*)d_in[8];
    const float* ba1    = (const float*)d_in[9];
    const float* Wa2    = (const float*)d_in[10];
    const float* ba2    = (const float*)d_in[11];
    const float* gammas = (const float*)d_in[12];
    const float* betas  = (const float*)d_in[13];
    float* out = (float*)d_out;

    pack_k<<<(256 * XPW + 255) / 256, 256>>>(W, Wa1, 0);
    pack_k<<<(256 * XPW + 255) / 256, 256>>>(U, Ua1, 1);
    initmask_k<<<NROWS / 256, 256>>>(maskp);

    // embedding: g_hseq = permute(x) @ W_emb + b_emb   (N = 256)
    gemm_k<<<dim3(2, 256), 256>>>(x, W_emb, b_emb, 256, 0);

    for (int d = 0; d < NDEPTH; d++) {
        // g_xpz = g_hseq @ [W | Wa1]   (N = 896)
        gemm_k<<<dim3(7, 256), 256>>>(nullptr, nullptr, nullptr, XPW, 1);
        // LN over first 768 cols with gamma0/beta0
        lnx_k<<<NROWS, 256>>>(gammas, betas);
        // recurrent scan (updates g_hseq, g_mask; writes action/policy)
        scan_k<<<32, 256>>>(b, ba1, Wa2, ba2, gammas + H3, betas + H3,
                            out, out_size, d);
    }

    copyout_k<<<64, 256>>>(out, out_size);
}

// round 10
// speedup vs baseline: 1.7805x; 1.7805x over previous
#include <cuda_runtime.h>
#include <math.h>
#include <stdint.h>

// ---------------------------------------------------------------------------
// Problem constants (fixed by setup_inputs)
// ---------------------------------------------------------------------------
#define Bn 64
#define Ln 512
#define Hn 256
#define H3 768
#define An 128
#define NDEPTH 4
#define NROWS (Ln * Bn)          /* 32768, t-major: row = t*Bn + b */
#define XPW 896                  /* 768 (gru proj) + 128 (action proj) */
#define OUT_ACT 16384            /* Bn*Hn */
#define OUT_POL 147456           /* OUT_ACT + Bn*NDEPTH*Ln */

#define CSIZE 8                  /* cluster size */
#define SLOTS 112                /* U columns per CTA (96 gru + 16 action) */
#define GRUS 96

// Dynamic smem layout for scan (float offsets)
#define SM_US   0                /* 256*112 = 28672 */
#define SM_HS   28672            /* float4[256] = 1024 floats (h, 4 rows) */
#define SM_ZB   29696            /* 112 slots * 4 rows = 448 */
#define SM_AP   30144            /* 16 * 4 = 64 (tanh action activations) */
#define SM_WR   30208            /* 4 warps * 4 rows * 2 = 32 */
#define SM_PB   30240            /* 8 ranks * 4 rows * 4 = 128 */
#define SM_AW0  30368            /* 16 */
#define SM_AW1  30384            /* 16 */
#define SM_AB1  30400            /* 16 */
#define SM_BA2  30416            /* 2 */
#define SM_TOT  30420
#define SCAN_SMEM (SM_TOT * 4)

// ---------------------------------------------------------------------------
// Static scratch
// ---------------------------------------------------------------------------
__device__ float g_hseq[NROWS * Hn];                 // 32 MB
__device__ float g_xpz[(size_t)NROWS * XPW];         // 112 MB
__device__ float g_wpack[256 * XPW];                 // [W | W_action_1]
__device__ float g_upack[256 * XPW];                 // [U | Ua1], cluster-slot layout
__device__ unsigned char g_maskA[NROWS];
__device__ unsigned char g_maskB[NROWS];

// ---------------------------------------------------------------------------
// PTX helpers (cluster / DSMEM)
// ---------------------------------------------------------------------------
__device__ __forceinline__ uint32_t smem_u32(const void* p) {
    uint32_t a;
    asm("{ .reg .u64 t; cvta.to.shared.u64 t, %1; cvt.u32.u64 %0, t; }"
        : "=r"(a) : "l"(p));
    return a;
}
__device__ __forceinline__ uint32_t mapa_c(uint32_t a, uint32_t r) {
    uint32_t d;
    asm("mapa.shared::cluster.u32 %0, %1, %2;" : "=r"(d) : "r"(a), "r"(r));
    return d;
}
__device__ __forceinline__ void stc(uint32_t a, float v) {
    asm volatile("st.shared::cluster.f32 [%0], %1;" :: "r"(a), "f"(v) : "memory");
}
__device__ __forceinline__ void cbar() {
    asm volatile("barrier.cluster.arrive.aligned;" ::: "memory");
    asm volatile("barrier.cluster.wait.aligned;" ::: "memory");
}
__device__ __forceinline__ uint32_t ctarank() {
    uint32_t r; asm("mov.u32 %0, %%cluster_ctarank;" : "=r"(r)); return r;
}

// ---------------------------------------------------------------------------
// Pack weights. which=0: g_wpack = [W | Wa1] plain [k][896].
// which=1: g_upack in cluster layout: col c -> (rank, slot); dst[k*896 + rank*112 + s]
//   gru  c<768 : rank = c&7,  s = c>>3          (s in [0,96))
//   act  a=c-768: rank = a&7, s = 96 + (a>>3)   (s in [96,112))
// ---------------------------------------------------------------------------
__global__ void pack_k(const float* __restrict__ Wm,
                       const float* __restrict__ Wa, int which)
{
    int i = blockIdx.x * blockDim.x + threadIdx.x;
    if (i >= 256 * XPW) return;
    int k = i / XPW, c = i % XPW;
    float v = (c < H3) ? Wm[k * H3 + c] : Wa[k * An + (c - H3)];
    if (which == 0) {
        g_wpack[i] = v;
    } else {
        int rank, s;
        if (c < H3) { rank = c & 7; s = c >> 3; }
        else        { int a = c - H3; rank = a & 7; s = GRUS + (a >> 3); }
        g_upack[k * XPW + rank * SLOTS + s] = v;
    }
}

__global__ void initmask_k(const int* __restrict__ m)
{
    int i = blockIdx.x * blockDim.x + threadIdx.x;
    if (i < NROWS) {
        int t = i >> 6, b = i & 63;
        g_maskA[i] = (m[b * Ln + t] != 0) ? 1 : 0;
    }
}

// ---------------------------------------------------------------------------
// GEMM: C[32768 x N] = A[32768 x 256] @ B[256 x N] (+ bias)   (unchanged)
// ---------------------------------------------------------------------------
__global__ void __launch_bounds__(256) gemm_k(
    const float* __restrict__ Aex, const float* __restrict__ Bex,
    const float* __restrict__ bias, int N, int mode)
{
    const float* __restrict__ A = mode ? g_hseq : Aex;
    const float* __restrict__ B = mode ? g_wpack : Bex;
    float* __restrict__ C       = mode ? g_xpz  : g_hseq;
    const int permute = (mode == 0);

    __shared__ __align__(16) float As[16][132];
    __shared__ __align__(16) float Bs[16][128];

    const int tid = threadIdx.x;
    const int bx = blockIdx.x, by = blockIdx.y;
    const int tx = tid & 15, ty = tid >> 4;

    float acc[8][8];
#pragma unroll
    for (int i = 0; i < 8; i++)
#pragma unroll
        for (int j = 0; j < 8; j++) acc[i][j] = 0.0f;

    const int ar  = tid & 127;
    const int akh = (tid >> 7) * 8;
    const int brow = tid >> 4;
    const int bcol = (tid & 15) * 8;

    for (int kt = 0; kt < 256; kt += 16) {
        int m = by * 128 + ar;
        long arow = permute ? ((long)(m & 63) * Ln + (m >> 6)) : (long)m;
        const float* ap = A + arow * 256 + kt + akh;
        float4 a0 = *(const float4*)ap;
        float4 a1 = *(const float4*)(ap + 4);
        As[akh + 0][ar] = a0.x; As[akh + 1][ar] = a0.y;
        As[akh + 2][ar] = a0.z; As[akh + 3][ar] = a0.w;
        As[akh + 4][ar] = a1.x; As[akh + 5][ar] = a1.y;
        As[akh + 6][ar] = a1.z; As[akh + 7][ar] = a1.w;

        const float* bp = B + (long)(kt + brow) * N + bx * 128 + bcol;
        *(float4*)&Bs[brow][bcol]     = *(const float4*)bp;
        *(float4*)&Bs[brow][bcol + 4] = *(const float4*)(bp + 4);
        __syncthreads();

#pragma unroll
        for (int kk = 0; kk < 16; kk++) {
            float a8[8], b8[8];
            *(float4*)&a8[0] = *(const float4*)&As[kk][ty * 8];
            *(float4*)&a8[4] = *(const float4*)&As[kk][ty * 8 + 4];
            *(float4*)&b8[0] = *(const float4*)&Bs[kk][tx * 8];
            *(float4*)&b8[4] = *(const float4*)&Bs[kk][tx * 8 + 4];
#pragma unroll
            for (int i = 0; i < 8; i++)
#pragma unroll
                for (int j = 0; j < 8; j++)
                    acc[i][j] = fmaf(a8[i], b8[j], acc[i][j]);
        }
        __syncthreads();
    }

    float bv[8];
#pragma unroll
    for (int j = 0; j < 8; j++)
        bv[j] = bias ? bias[bx * 128 + tx * 8 + j] : 0.0f;

#pragma unroll
    for (int i = 0; i < 8; i++) {
        long row = by * 128 + ty * 8 + i;
        float* cp = C + row * N + bx * 128 + tx * 8;
        float4 o0, o1;
        o0.x = acc[i][0] + bv[0]; o0.y = acc[i][1] + bv[1];
        o0.z = acc[i][2] + bv[2]; o0.w = acc[i][3] + bv[3];
        o1.x = acc[i][4] + bv[4]; o1.y = acc[i][5] + bv[5];
        o1.z = acc[i][6] + bv[6]; o1.w = acc[i][7] + bv[7];
        *(float4*)cp       = o0;
        *(float4*)(cp + 4) = o1;
    }
}

// ---------------------------------------------------------------------------
// Row LayerNorm of g_xpz[:, 0:768] in place (gamma0/beta0). 1 block/row.
// ---------------------------------------------------------------------------
__global__ void __launch_bounds__(256) lnx_k(const float* __restrict__ gam,
                                             const float* __restrict__ bet)
{
    long row = blockIdx.x;
    float* p = g_xpz + row * XPW;
    int tid = threadIdx.x;
    float v0 = p[tid], v1 = p[tid + 256], v2 = p[tid + 512];
    float s = v0 + v1 + v2;
    float q = v0 * v0 + v1 * v1 + v2 * v2;

    __shared__ float rs[8], rq[8], st[2];
#pragma unroll
    for (int off = 16; off; off >>= 1) {
        s += __shfl_down_sync(0xffffffffu, s, off);
        q += __shfl_down_sync(0xffffffffu, q, off);
    }
    if ((tid & 31) == 0) { rs[tid >> 5] = s; rq[tid >> 5] = q; }
    __syncthreads();
    if (tid == 0) {
        float S = 0.f, Q = 0.f;
#pragma unroll
        for (int i = 0; i < 8; i++) { S += rs[i]; Q += rq[i]; }
        float mean = S * (1.0f / 768.0f);
        float var  = Q * (1.0f / 768.0f) - mean * mean;
        st[0] = mean;
        st[1] = rsqrtf(var + 1e-5f);
    }
    __syncthreads();
    float mean = st[0], r = st[1];
    p[tid]       = (v0 - mean) * r * gam[tid]       + bet[tid];
    p[tid + 256] = (v1 - mean) * r * gam[tid + 256] + bet[tid + 256];
    p[tid + 512] = (v2 - mean) * r * gam[tid + 512] + bet[tid + 512];
}

// ---------------------------------------------------------------------------
// Cluster scan: 16 clusters x 8 CTAs; cluster handles 4 batch rows for all
// 512 steps. CTA rank i owns U columns c == i (mod 8), SMEM-resident.
// Per step: local GEMV slice -> partial exchange (DSMEM) -> cluster barrier
// -> gates/h-update local (triple co-located mod 8) -> h broadcast -> barrier.
// ---------------------------------------------------------------------------
__global__ void __launch_bounds__(256, 1) __cluster_dims__(CSIZE, 1, 1)
scan_k(const float* __restrict__ bias3, const float* __restrict__ ba1,
       const float* __restrict__ wa2,   const float* __restrict__ ba2,
       const float* __restrict__ gam1,  const float* __restrict__ bet1,
       float* __restrict__ out, int out_size, int dep, int ping)
{
    extern __shared__ float sm[];
    float*  us  = sm + SM_US;
    float*  hsf = sm + SM_HS;          // float4[256] viewed as floats
    float*  zb  = sm + SM_ZB;
    float*  ap  = sm + SM_AP;
    float*  wrd = sm + SM_WR;
    float*  pb  = sm + SM_PB;
    float*  aw0 = sm + SM_AW0;
    float*  aw1 = sm + SM_AW1;
    float*  ab1 = sm + SM_AB1;
    float*  b2s = sm + SM_BA2;

    const int tid = threadIdx.x;
    const uint32_t rank = ctarank();
    const int bbase = (blockIdx.x / CSIZE) * 4;      // 4 batch rows per cluster
    const uint32_t sm32 = smem_u32(sm);

    const unsigned char* __restrict__ min_ = ping ? g_maskB : g_maskA;
    unsigned char* __restrict__       mout = ping ? g_maskA : g_maskB;

    // Load this CTA's U slice (coalesced: cluster layout in g_upack)
    for (int idx = tid; idx < 256 * SLOTS / 4; idx += 256) {
        int k = idx / (SLOTS / 4), s4 = (idx % (SLOTS / 4)) * 4;
        *(float4*)&us[k * SLOTS + s4] =
            *(const float4*)&g_upack[k * XPW + rank * SLOTS + s4];
    }
    // Per-thread gate constants (col c = 8j + rank, row r)
    float cg0=0,cg1=0,cg2=0, ce0=0,ce1=0,ce2=0, cb0=0,cb1=0,cb2=0;
    int myc = 0, myrow = 0;
    if (tid < 128) {
        int j = tid >> 2, r = tid & 3;
        myc = 8 * j + (int)rank;
        myrow = bbase + r;
        cg0 = gam1[myc]; cg1 = gam1[myc + 256]; cg2 = gam1[myc + 512];
        ce0 = bet1[myc]; ce1 = bet1[myc + 256]; ce2 = bet1[myc + 512];
        cb0 = bias3[myc]; cb1 = bias3[myc + 256]; cb2 = bias3[myc + 512];
    }
    if (tid < 16) {
        int a = 8 * tid + (int)rank;
        aw0[tid] = wa2[a * 2]; aw1[tid] = wa2[a * 2 + 1]; ab1[tid] = ba1[a];
    }
    if (tid < 2) b2s[tid] = ba2[tid];
    // h0 = 0
    hsf[tid * 4 + 0] = 0.f; hsf[tid * 4 + 1] = 0.f;
    hsf[tid * 4 + 2] = 0.f; hsf[tid * 4 + 3] = 0.f;
    float hprev = 0.0f;
    __syncthreads();

    const int s  = (tid < 224) ? (tid % SLOTS) : 0;   // GEMV slot
    const int rp = (tid < 224) ? (tid / SLOTS) : 0;   // row pair (0: rows 0,1; 1: rows 2,3)

    for (int t = 0; t < Ln; t++) {
        // -------- prefetch (hidden under GEMV) --------
        float xp0 = 0.f, xp1 = 0.f, xp2 = 0.f; int mt = 0;
        if (tid < 128) {
            long base = (long)(t * Bn + myrow) * XPW;
            xp0 = g_xpz[base + myc];
            xp1 = g_xpz[base + myc + 256];
            xp2 = g_xpz[base + myc + 512];
            mt  = min_[t * Bn + myrow];
        }
        float xa0 = 0.f, xa1 = 0.f;
        if (tid < 224 && s >= GRUS) {
            int a = 8 * (s - GRUS) + (int)rank;
            long b0 = (long)(t * Bn + bbase + 2 * rp) * XPW + H3 + a;
            xa0 = g_xpz[b0];
            xa1 = g_xpz[b0 + XPW];
        }

        // -------- GEMV: z[s] = sum_k h[k] * U[k][col(s)] for 2 rows --------
        if (tid < 224) {
            float a0 = 0.f, a1 = 0.f;
            const float*  up = us + s;
            const float2* hp = ((const float2*)hsf) + rp;
#pragma unroll 8
            for (int k = 0; k < 256; k++) {
                float  u  = up[k * SLOTS];
                float2 h2 = hp[k * 2];
                a0 = fmaf(u, h2.x, a0);
                a1 = fmaf(u, h2.y, a1);
            }
            if (s < GRUS) {
                zb[s * 4 + 2 * rp]     = a0;
                zb[s * 4 + 2 * rp + 1] = a1;
            } else {
                int q = s - GRUS; float bb = ab1[q];
                ap[q * 4 + 2 * rp]     = tanhf(xa0 + a0 + bb);
                ap[q * 4 + 2 * rp + 1] = tanhf(xa1 + a1 + bb);
            }
        }
        __syncthreads();

        // -------- local LN partials (thread (j,r) reads its z triple) --------
        float z0 = 0.f, z1 = 0.f, z2 = 0.f;
        if (tid < 128) {
            z0 = zb[tid]; z1 = zb[tid + 128]; z2 = zb[tid + 256];
            float sv = z0 + z1 + z2;
            float qv = z0 * z0 + z1 * z1 + z2 * z2;
#pragma unroll
            for (int o = 4; o < 32; o <<= 1) {
                sv += __shfl_xor_sync(0xffffffffu, sv, o);
                qv += __shfl_xor_sync(0xffffffffu, qv, o);
            }
            if ((tid & 31) < 4) {
                int w = tid >> 5, r = tid & 3;
                wrd[w * 8 + r * 2]     = sv;
                wrd[w * 8 + r * 2 + 1] = qv;
            }
        }
        __syncthreads();

        // -------- CTA-local sums -> broadcast partials to all 8 CTAs --------
        if (tid < 4) {
            int r = tid;
            float sv = wrd[r*2] + wrd[8 + r*2] + wrd[16 + r*2] + wrd[24 + r*2];
            float qv = wrd[r*2+1] + wrd[8 + r*2+1] + wrd[16 + r*2+1] + wrd[24 + r*2+1];
            uint32_t loc = sm32 + (uint32_t)(SM_PB + (rank * 4 + r) * 4) * 4u;
#pragma unroll
            for (uint32_t ii = 0; ii < CSIZE; ii++) {
                uint32_t pa = mapa_c(loc, ii);
                stc(pa, sv); stc(pa + 4, qv);
            }
        } else if (tid >= 224 && tid < 228) {
            int r = tid - 224;
            float l0 = 0.f, l1 = 0.f;
#pragma unroll
            for (int q = 0; q < 16; q++) {
                float tq = ap[q * 4 + r];
                l0 = fmaf(tq, aw0[q], l0);
                l1 = fmaf(tq, aw1[q], l1);
            }
            uint32_t loc = sm32 + (uint32_t)(SM_PB + (rank * 4 + r) * 4 + 2) * 4u;
#pragma unroll
            for (uint32_t ii = 0; ii < CSIZE; ii++) {
                uint32_t pa = mapa_c(loc, ii);
                stc(pa, l0); stc(pa + 4, l1);
            }
        }
        cbar();   // partials visible; all GEMV reads of hs done

        // -------- gates + h update (local triple), h broadcast --------
        if (tid < 128) {
            int r = tid & 3;
            float S = 0.f, Q = 0.f;
#pragma unroll
            for (int ii = 0; ii < CSIZE; ii++) {
                S += pb[(ii * 4 + r) * 4];
                Q += pb[(ii * 4 + r) * 4 + 1];
            }
            float mean = S * (1.0f / 768.0f);
            float var  = Q * (1.0f / 768.0f) - mean * mean;
            float rstd = rsqrtf(var + 1e-5f);
            float hp0 = (z0 - mean) * rstd * cg0 + ce0;
            float hp1 = (z1 - mean) * rstd * cg1 + ce1;
            float hp2 = (z2 - mean) * rstd * cg2 + ce2;
            float rg = 1.0f / (1.0f + expf(-(xp0 + hp0 + cb0)));
            float zg = 1.0f / (1.0f + expf(-(xp1 + hp1 + cb1)));
            float hh = tanhf(xp2 + rg * hp2 + cb2);
            float hn = zg * hprev + (1.0f - zg) * hh;
            float ho = mt ? hn : hprev;
            hprev = ho;
            g_hseq[(long)(t * Bn + myrow) * Hn + myc] = ho;
            uint32_t loc = sm32 + (uint32_t)(SM_HS + myc * 4 + r) * 4u;
#pragma unroll
            for (uint32_t ii = 0; ii < CSIZE; ii++)
                stc(mapa_c(loc, ii), ho);
        } else if (tid >= 224 && tid < 228) {
            int r = tid - 224;
            float l0 = b2s[0], l1 = b2s[1];
#pragma unroll
            for (int ii = 0; ii < CSIZE; ii++) {
                l0 += pb[(ii * 4 + r) * 4 + 2];
                l1 += pb[(ii * 4 + r) * 4 + 3];
            }
            int b = bbase + r;
            int m = min_[t * Bn + b];
            int act = (l1 > l0) && m;    // pol1>pol0 <=> l1>l0 (softmax monotone)
            if (rank == 0) {
                float mx = fmaxf(l0, l1);
                float e0 = expf(l0 - mx), e1 = expf(l1 - mx);
                float inv = 1.0f / (e0 + e1);
                int ai = OUT_ACT + (b * NDEPTH + dep) * Ln + t;
                if (ai < out_size) out[ai] = (float)act;
                int pi = OUT_POL + ((b * NDEPTH + dep) * Ln + t) * 2;
                if (pi + 1 < out_size) { out[pi] = e0 * inv; out[pi + 1] = e1 * inv; }
                mout[t * Bn + b] = (unsigned char)act;   // act already includes & m
            }
        }
        cbar();   // h(t) visible in every CTA's hs
    }
}

// ---------------------------------------------------------------------------
// output = h_seq[-1] (t = 511), (B, H)
// ---------------------------------------------------------------------------
__global__ void copyout_k(float* __restrict__ out, int out_size)
{
    int i = blockIdx.x * blockDim.x + threadIdx.x;
    if (i < Bn * Hn && i < out_size)
        out[i] = g_hseq[(long)(511 * Bn + (i >> 8)) * Hn + (i & 255)];
}

// ---------------------------------------------------------------------------
// launch
// ---------------------------------------------------------------------------
extern "C" void kernel_launch(void* const* d_in, const int* in_sizes, int n_in,
                              void* d_out, int out_size)
{
    const float* x      = (const float*)d_in[0];
    const int*   maskp  = (const int*)  d_in[1];
    const float* W_emb  = (const float*)d_in[2];
    const float* b_emb  = (const float*)d_in[3];
    const float* W      = (const float*)d_in[4];
    const float* U      = (const float*)d_in[5];
    const float* b      = (const float*)d_in[6];
    const float* Wa1    = (const float*)d_in[7];
    const float* Ua1    = (const float*)d_in[8];
    const float* ba1    = (const float*)d_in[9];
    const float* Wa2    = (const float*)d_in[10];
    const float* ba2    = (const float*)d_in[11];
    const float* gammas = (const float*)d_in[12];
    const float* betas  = (const float*)d_in[13];
    float* out = (float*)d_out;

    static int attr_done = 0;
    if (!attr_done) {
        cudaFuncSetAttribute(scan_k, cudaFuncAttributeMaxDynamicSharedMemorySize,
                             SCAN_SMEM);
        attr_done = 1;
    }

    pack_k<<<(256 * XPW + 255) / 256, 256>>>(W, Wa1, 0);
    pack_k<<<(256 * XPW + 255) / 256, 256>>>(U, Ua1, 1);
    initmask_k<<<NROWS / 256, 256>>>(maskp);

    // embedding: g_hseq = permute(x) @ W_emb + b_emb
    gemm_k<<<dim3(2, 256), 256>>>(x, W_emb, b_emb, 256, 0);

    for (int d = 0; d < NDEPTH; d++) {
        gemm_k<<<dim3(7, 256), 256>>>(nullptr, nullptr, nullptr, XPW, 1);
        lnx_k<<<NROWS, 256>>>(gammas, betas);
        scan_k<<<128, 256, SCAN_SMEM>>>(b, ba1, Wa2, ba2,
                                        gammas + H3, betas + H3,
                                        out, out_size, d, d & 1);
    }

    copyout_k<<<64, 256>>>(out, out_size);
}

// round 11
// speedup vs baseline: 1.9999x; 1.1232x over previous
#include <cuda_runtime.h>
#include <math.h>
#include <stdint.h>

// ---------------------------------------------------------------------------
// Problem constants (fixed by setup_inputs)
// ---------------------------------------------------------------------------
#define Bn 64
#define Ln 512
#define Hn 256
#define H3 768
#define An 128
#define NDEPTH 4
#define NROWS (Ln * Bn)          /* 32768, t-major: row = t*Bn + b */
#define XPW 896                  /* 768 (gru proj) + 128 (action proj) */
#define OUT_ACT 16384            /* Bn*Hn */
#define OUT_POL 147456           /* OUT_ACT + Bn*NDEPTH*Ln */

#define CSIZE 8                  /* cluster size */
#define SLOTS 112                /* U columns per CTA (96 gru + 16 action) */
#define GRUS 96

// Static smem layout for scan (float offsets)
#define SM_HS   0                /* h: [row][k] 4*256 = 1024 */
#define SM_PART 1024             /* split-k partials: 448 * 4 = 1792 */
#define SM_ZB   2816             /* z: 112 slots * 5 (pad) = 560 */
#define SM_AP   3376             /* tanh action acts: 16 * 4 = 64 */
#define SM_PB   3440             /* 8 ranks * 4 rows * 4 = 128 */
#define SM_AW0  3568             /* 16 */
#define SM_AW1  3584             /* 16 */
#define SM_AB1  3600             /* 16 */
#define SM_BA2  3616             /* 2 */
#define SM_TOT  3620             /* 14480 bytes */

// ---------------------------------------------------------------------------
// Static scratch
// ---------------------------------------------------------------------------
__device__ float g_hseq[NROWS * Hn];                 // 32 MB
__device__ float g_xpz[(size_t)NROWS * XPW];         // 112 MB
__device__ float g_wpack[256 * XPW];                 // [W | W_action_1]
__device__ float g_upack[256 * XPW];                 // [rank][slot][k] layout
__device__ unsigned char g_maskA[NROWS];
__device__ unsigned char g_maskB[NROWS];

// ---------------------------------------------------------------------------
// PTX helpers (cluster / DSMEM)
// ---------------------------------------------------------------------------
__device__ __forceinline__ uint32_t smem_u32(const void* p) {
    uint32_t a;
    asm("{ .reg .u64 t; cvta.to.shared.u64 t, %1; cvt.u32.u64 %0, t; }"
        : "=r"(a) : "l"(p));
    return a;
}
__device__ __forceinline__ uint32_t mapa_c(uint32_t a, uint32_t r) {
    uint32_t d;
    asm("mapa.shared::cluster.u32 %0, %1, %2;" : "=r"(d) : "r"(a), "r"(r));
    return d;
}
__device__ __forceinline__ void stc(uint32_t a, float v) {
    asm volatile("st.shared::cluster.f32 [%0], %1;" :: "r"(a), "f"(v) : "memory");
}
__device__ __forceinline__ void carrive() {
    asm volatile("barrier.cluster.arrive.aligned;" ::: "memory");
}
__device__ __forceinline__ void cwait() {
    asm volatile("barrier.cluster.wait.aligned;" ::: "memory");
}
__device__ __forceinline__ uint32_t ctarank() {
    uint32_t r; asm("mov.u32 %0, %%cluster_ctarank;" : "=r"(r)); return r;
}

// ---------------------------------------------------------------------------
// Pack weights.
// which=0: g_wpack = [W | Wa1] plain [k][896].
// which=1: g_upack[((rank*112 + slot)*256) + k] = U/Ua1[k][c]
//   gru  c<768 : rank = c&7, slot = c>>3
//   act  a=c-768: rank = a&7, slot = 96 + (a>>3)
// ---------------------------------------------------------------------------
__global__ void pack_k(const float* __restrict__ Wm,
                       const float* __restrict__ Wa, int which)
{
    int i = blockIdx.x * blockDim.x + threadIdx.x;
    if (i >= 256 * XPW) return;
    int k = i / XPW, c = i % XPW;
    float v = (c < H3) ? Wm[k * H3 + c] : Wa[k * An + (c - H3)];
    if (which == 0) {
        g_wpack[i] = v;
    } else {
        int rank, s;
        if (c < H3) { rank = c & 7; s = c >> 3; }
        else        { int a = c - H3; rank = a & 7; s = GRUS + (a >> 3); }
        g_upack[(rank * SLOTS + s) * 256 + k] = v;
    }
}

__global__ void initmask_k(const int* __restrict__ m)
{
    int i = blockIdx.x * blockDim.x + threadIdx.x;
    if (i < NROWS) {
        int t = i >> 6, b = i & 63;
        g_maskA[i] = (m[b * Ln + t] != 0) ? 1 : 0;
    }
}

// ---------------------------------------------------------------------------
// GEMM: C[32768 x N] = A[32768 x 256] @ B[256 x N] (+ bias)   (unchanged)
// ---------------------------------------------------------------------------
__global__ void __launch_bounds__(256) gemm_k(
    const float* __restrict__ Aex, const float* __restrict__ Bex,
    const float* __restrict__ bias, int N, int mode)
{
    const float* __restrict__ A = mode ? g_hseq : Aex;
    const float* __restrict__ B = mode ? g_wpack : Bex;
    float* __restrict__ C       = mode ? g_xpz  : g_hseq;
    const int permute = (mode == 0);

    __shared__ __align__(16) float As[16][132];
    __shared__ __align__(16) float Bs[16][128];

    const int tid = threadIdx.x;
    const int bx = blockIdx.x, by = blockIdx.y;
    const int tx = tid & 15, ty = tid >> 4;

    float acc[8][8];
#pragma unroll
    for (int i = 0; i < 8; i++)
#pragma unroll
        for (int j = 0; j < 8; j++) acc[i][j] = 0.0f;

    const int ar  = tid & 127;
    const int akh = (tid >> 7) * 8;
    const int brow = tid >> 4;
    const int bcol = (tid & 15) * 8;

    for (int kt = 0; kt < 256; kt += 16) {
        int m = by * 128 + ar;
        long arow = permute ? ((long)(m & 63) * Ln + (m >> 6)) : (long)m;
        const float* ap = A + arow * 256 + kt + akh;
        float4 a0 = *(const float4*)ap;
        float4 a1 = *(const float4*)(ap + 4);
        As[akh + 0][ar] = a0.x; As[akh + 1][ar] = a0.y;
        As[akh + 2][ar] = a0.z; As[akh + 3][ar] = a0.w;
        As[akh + 4][ar] = a1.x; As[akh + 5][ar] = a1.y;
        As[akh + 6][ar] = a1.z; As[akh + 7][ar] = a1.w;

        const float* bp = B + (long)(kt + brow) * N + bx * 128 + bcol;
        *(float4*)&Bs[brow][bcol]     = *(const float4*)bp;
        *(float4*)&Bs[brow][bcol + 4] = *(const float4*)(bp + 4);
        __syncthreads();

#pragma unroll
        for (int kk = 0; kk < 16; kk++) {
            float a8[8], b8[8];
            *(float4*)&a8[0] = *(const float4*)&As[kk][ty * 8];
            *(float4*)&a8[4] = *(const float4*)&As[kk][ty * 8 + 4];
            *(float4*)&b8[0] = *(const float4*)&Bs[kk][tx * 8];
            *(float4*)&b8[4] = *(const float4*)&Bs[kk][tx * 8 + 4];
#pragma unroll
            for (int i = 0; i < 8; i++)
#pragma unroll
                for (int j = 0; j < 8; j++)
                    acc[i][j] = fmaf(a8[i], b8[j], acc[i][j]);
        }
        __syncthreads();
    }

    float bv[8];
#pragma unroll
    for (int j = 0; j < 8; j++)
        bv[j] = bias ? bias[bx * 128 + tx * 8 + j] : 0.0f;

#pragma unroll
    for (int i = 0; i < 8; i++) {
        long row = by * 128 + ty * 8 + i;
        float* cp = C + row * N + bx * 128 + tx * 8;
        float4 o0, o1;
        o0.x = acc[i][0] + bv[0]; o0.y = acc[i][1] + bv[1];
        o0.z = acc[i][2] + bv[2]; o0.w = acc[i][3] + bv[3];
        o1.x = acc[i][4] + bv[4]; o1.y = acc[i][5] + bv[5];
        o1.z = acc[i][6] + bv[6]; o1.w = acc[i][7] + bv[7];
        *(float4*)cp       = o0;
        *(float4*)(cp + 4) = o1;
    }
}

// ---------------------------------------------------------------------------
// Row LayerNorm of g_xpz[:, 0:768] in place (gamma0/beta0). 1 block/row.
// ---------------------------------------------------------------------------
__global__ void __launch_bounds__(256) lnx_k(const float* __restrict__ gam,
                                             const float* __restrict__ bet)
{
    long row = blockIdx.x;
    float* p = g_xpz + row * XPW;
    int tid = threadIdx.x;
    float v0 = p[tid], v1 = p[tid + 256], v2 = p[tid + 512];
    float s = v0 + v1 + v2;
    float q = v0 * v0 + v1 * v1 + v2 * v2;

    __shared__ float rs[8], rq[8], st[2];
#pragma unroll
    for (int off = 16; off; off >>= 1) {
        s += __shfl_down_sync(0xffffffffu, s, off);
        q += __shfl_down_sync(0xffffffffu, q, off);
    }
    if ((tid & 31) == 0) { rs[tid >> 5] = s; rq[tid >> 5] = q; }
    __syncthreads();
    if (tid == 0) {
        float S = 0.f, Q = 0.f;
#pragma unroll
        for (int i = 0; i < 8; i++) { S += rs[i]; Q += rq[i]; }
        float mean = S * (1.0f / 768.0f);
        float var  = Q * (1.0f / 768.0f) - mean * mean;
        st[0] = mean;
        st[1] = rsqrtf(var + 1e-5f);
    }
    __syncthreads();
    float mean = st[0], r = st[1];
    p[tid]       = (v0 - mean) * r * gam[tid]       + bet[tid];
    p[tid + 256] = (v1 - mean) * r * gam[tid + 256] + bet[tid + 256];
    p[tid + 512] = (v2 - mean) * r * gam[tid + 512] + bet[tid + 512];
}

// ---------------------------------------------------------------------------
// Cluster scan v2: 16 clusters x 8 CTAs x 512 threads. Cluster owns 4 batch
// rows for all 512 steps. CTA rank i owns U columns c == i (mod 8), held in
// REGISTERS (448 threads = 112 slots x 4 k-quarters, 16 float4 each).
// h is smem [row][k] and broadcast to all 8 CTAs via DSMEM each step.
// ---------------------------------------------------------------------------
__global__ void __launch_bounds__(512, 1) __cluster_dims__(CSIZE, 1, 1)
scan_k(const float* __restrict__ bias3, const float* __restrict__ ba1,
       const float* __restrict__ wa2,   const float* __restrict__ ba2,
       const float* __restrict__ gam1,  const float* __restrict__ bet1,
       float* __restrict__ out, int out_size, int dep, int ping)
{
    __shared__ __align__(16) float sm[SM_TOT];
    float* hsf = sm + SM_HS;
    float* part = sm + SM_PART;
    float* zb  = sm + SM_ZB;
    float* ap  = sm + SM_AP;
    float* pb  = sm + SM_PB;
    float* aw0 = sm + SM_AW0;
    float* aw1 = sm + SM_AW1;
    float* ab1 = sm + SM_AB1;
    float* b2s = sm + SM_BA2;

    const int tid = threadIdx.x;
    const uint32_t rank = ctarank();
    const int bbase = (blockIdx.x / CSIZE) * 4;
    const uint32_t sm32 = smem_u32(sm);

    const unsigned char* __restrict__ min_ = ping ? g_maskB : g_maskA;
    unsigned char* __restrict__       mout = ping ? g_maskA : g_maskB;

    // ---- GEMV thread identity + U registers (64 floats) ----
    const int gs = tid % SLOTS;          // slot (valid when tid<448)
    const int gq = tid / SLOTS;          // k-quarter
    float4 uq[16];
    if (tid < 448) {
        const float4* up = (const float4*)(g_upack + ((rank * SLOTS + gs) * 256 + gq * 64));
#pragma unroll
        for (int i = 0; i < 16; i++) uq[i] = up[i];
    }

    // ---- gate thread identity (tid<128): warp r = tid>>5, lane j = tid&31
    float cg0=0,cg1=0,cg2=0, ce0=0,ce1=0,ce2=0, cb0=0,cb1=0,cb2=0;
    int myc = 0, myrow = 0;
    if (tid < 128) {
        int r = tid >> 5, j = tid & 31;
        myc = 8 * j + (int)rank;
        myrow = bbase + r;
        cg0 = gam1[myc]; cg1 = gam1[myc + 256]; cg2 = gam1[myc + 512];
        ce0 = bet1[myc]; ce1 = bet1[myc + 256]; ce2 = bet1[myc + 512];
        cb0 = bias3[myc]; cb1 = bias3[myc + 256]; cb2 = bias3[myc + 512];
    }
    if (tid < 16) {
        int a = 8 * tid + (int)rank;
        aw0[tid] = wa2[a * 2]; aw1[tid] = wa2[a * 2 + 1]; ab1[tid] = ba1[a];
    }
    if (tid < 2) b2s[tid] = ba2[tid];
    // h0 = 0
    hsf[tid] = 0.0f; hsf[tid + 512] = 0.0f;
    float hprev = 0.0f;
    __syncthreads();
    carrive();                       // matches the wait at top of iteration 0

    for (int t = 0; t < Ln; t++) {
        // -------- prefetch for later stages (issued before the cluster wait)
        float xp0 = 0.f, xp1 = 0.f, xp2 = 0.f; int mt = 0;
        if (tid < 128) {
            long base = (long)(t * Bn + myrow) * XPW;
            xp0 = g_xpz[base + myc];
            xp1 = g_xpz[base + myc + 256];
            xp2 = g_xpz[base + myc + 512];
            mt  = min_[t * Bn + myrow];
        }
        float xav = 0.f;
        if (tid >= 384 && tid < 448) {        // reduce-stage action threads
            int s2 = tid >> 2, r2 = tid & 3;
            int a = 8 * (s2 - GRUS) + (int)rank;
            xav = g_xpz[(long)(t * Bn + bbase + r2) * XPW + H3 + a];
        }
        int mtA = 0;
        if (tid >= 128 && tid < 132)
            mtA = min_[t * Bn + bbase + (tid - 128)];

        cwait();   // h(t-1) from all ranks visible

        // -------- GEMV quarter-dot: all 4 batch rows, 64 k's --------
        if (tid < 448) {
            float a0 = 0.f, a1 = 0.f, a2 = 0.f, a3 = 0.f;
            const float4* h0 = (const float4*)(hsf + gq * 64);
            const float4* h1 = (const float4*)(hsf + 256 + gq * 64);
            const float4* h2 = (const float4*)(hsf + 512 + gq * 64);
            const float4* h3 = (const float4*)(hsf + 768 + gq * 64);
#pragma unroll
            for (int i = 0; i < 16; i++) {
                float4 u4 = uq[i];
                float4 v0 = h0[i], v1 = h1[i], v2 = h2[i], v3 = h3[i];
                a0 = fmaf(u4.x, v0.x, a0); a0 = fmaf(u4.y, v0.y, a0);
                a0 = fmaf(u4.z, v0.z, a0); a0 = fmaf(u4.w, v0.w, a0);
                a1 = fmaf(u4.x, v1.x, a1); a1 = fmaf(u4.y, v1.y, a1);
                a1 = fmaf(u4.z, v1.z, a1); a1 = fmaf(u4.w, v1.w, a1);
                a2 = fmaf(u4.x, v2.x, a2); a2 = fmaf(u4.y, v2.y, a2);
                a2 = fmaf(u4.z, v2.z, a2); a2 = fmaf(u4.w, v2.w, a2);
                a3 = fmaf(u4.x, v3.x, a3); a3 = fmaf(u4.y, v3.y, a3);
                a3 = fmaf(u4.z, v3.z, a3); a3 = fmaf(u4.w, v3.w, a3);
            }
            ((float4*)part)[gq * SLOTS + gs] = make_float4(a0, a1, a2, a3);
        }
        __syncthreads();

        // -------- split-k reduce: z[slot][row] --------
        if (tid < 448) {
            int s2 = tid >> 2, r2 = tid & 3;
            const float* pp = part + s2 * 4 + r2;
            float z = pp[0] + pp[448] + pp[896] + pp[1344];
            if (s2 < GRUS) zb[s2 * 5 + r2] = z;
            else {
                int qa = s2 - GRUS;
                ap[qa * 4 + r2] = tanhf(xav + z + ab1[qa]);
            }
        }
        __syncthreads();

        // -------- LN partials (warp r handles row r) + action logits ------
        float z0 = 0.f, z1 = 0.f, z2 = 0.f;
        if (tid < 128) {
            int r = tid >> 5, j = tid & 31;
            z0 = zb[j * 5 + r];
            z1 = zb[(j + 32) * 5 + r];
            z2 = zb[(j + 64) * 5 + r];
            float sv = z0 + z1 + z2;
            float qv = z0 * z0 + z1 * z1 + z2 * z2;
#pragma unroll
            for (int o = 16; o; o >>= 1) {
                sv += __shfl_xor_sync(0xffffffffu, sv, o);
                qv += __shfl_xor_sync(0xffffffffu, qv, o);
            }
            if (j == 0) {
                uint32_t loc = sm32 + (uint32_t)(SM_PB + (rank * 4 + r) * 4) * 4u;
#pragma unroll
                for (uint32_t ii = 0; ii < CSIZE; ii++) {
                    uint32_t pa = mapa_c(loc, ii);
                    stc(pa, sv); stc(pa + 4, qv);
                }
            }
        } else if (tid < 132) {
            int r = tid - 128;
            float l0 = 0.f, l1 = 0.f;
#pragma unroll
            for (int q = 0; q < 16; q++) {
                float tq = ap[q * 4 + r];
                l0 = fmaf(tq, aw0[q], l0);
                l1 = fmaf(tq, aw1[q], l1);
            }
            uint32_t loc = sm32 + (uint32_t)(SM_PB + (rank * 4 + r) * 4 + 2) * 4u;
#pragma unroll
            for (uint32_t ii = 0; ii < CSIZE; ii++) {
                uint32_t pa = mapa_c(loc, ii);
                stc(pa, l0); stc(pa + 4, l1);
            }
        }
        carrive(); cwait();   // pb complete everywhere; hs reads all done

        // -------- gates + h update + broadcast --------
        if (tid < 128) {
            int r = tid >> 5;
            float S = 0.f, Q = 0.f;
#pragma unroll
            for (int ii = 0; ii < CSIZE; ii++) {
                S += pb[(ii * 4 + r) * 4];
                Q += pb[(ii * 4 + r) * 4 + 1];
            }
            float mean = S * (1.0f / 768.0f);
            float var  = Q * (1.0f / 768.0f) - mean * mean;
            float rstd = rsqrtf(var + 1e-5f);
            float hp0 = (z0 - mean) * rstd * cg0 + ce0;
            float hp1 = (z1 - mean) * rstd * cg1 + ce1;
            float hp2 = (z2 - mean) * rstd * cg2 + ce2;
            float rg = 1.0f / (1.0f + expf(-(xp0 + hp0 + cb0)));
            float zg = 1.0f / (1.0f + expf(-(xp1 + hp1 + cb1)));
            float hh = tanhf(xp2 + rg * hp2 + cb2);
            float hn = zg * hprev + (1.0f - zg) * hh;
            float ho = mt ? hn : hprev;
            hprev = ho;
            g_hseq[(long)(t * Bn + myrow) * Hn + myc] = ho;
            uint32_t loc = sm32 + (uint32_t)(SM_HS + r * 256 + myc) * 4u;
#pragma unroll
            for (uint32_t ii = 0; ii < CSIZE; ii++)
                stc(mapa_c(loc, ii), ho);
        } else if (tid < 132) {
            int r = tid - 128;
            float l0 = b2s[0], l1 = b2s[1];
#pragma unroll
            for (int ii = 0; ii < CSIZE; ii++) {
                l0 += pb[(ii * 4 + r) * 4 + 2];
                l1 += pb[(ii * 4 + r) * 4 + 3];
            }
            int b = bbase + r;
            int act = (l1 > l0) && mtA;   // pol1>pol0 <=> l1>l0 (softmax monotone)
            if (rank == 0) {
                float mx = fmaxf(l0, l1);
                float e0 = expf(l0 - mx), e1 = expf(l1 - mx);
                float inv = 1.0f / (e0 + e1);
                int ai = OUT_ACT + (b * NDEPTH + dep) * Ln + t;
                if (ai < out_size) out[ai] = (float)act;
                int pi = OUT_POL + ((b * NDEPTH + dep) * Ln + t) * 2;
                if (pi + 1 < out_size) { out[pi] = e0 * inv; out[pi + 1] = e1 * inv; }
                mout[t * Bn + b] = (unsigned char)act;
            }
        }
        carrive();   // h(t) release; matched by cwait at top of next iter
    }
    cwait();         // balance final arrive
}

// ---------------------------------------------------------------------------
// output = h_seq[-1] (t = 511), (B, H)
// ---------------------------------------------------------------------------
__global__ void copyout_k(float* __restrict__ out, int out_size)
{
    int i = blockIdx.x * blockDim.x + threadIdx.x;
    if (i < Bn * Hn && i < out_size)
        out[i] = g_hseq[(long)(511 * Bn + (i >> 8)) * Hn + (i & 255)];
}

// ---------------------------------------------------------------------------
// launch
// ---------------------------------------------------------------------------
extern "C" void kernel_launch(void* const* d_in, const int* in_sizes, int n_in,
                              void* d_out, int out_size)
{
    const float* x      = (const float*)d_in[0];
    const int*   maskp  = (const int*)  d_in[1];
    const float* W_emb  = (const float*)d_in[2];
    const float* b_emb  = (const float*)d_in[3];
    const float* W      = (const float*)d_in[4];
    const float* U      = (const float*)d_in[5];
    const float* b      = (const float*)d_in[6];
    const float* Wa1    = (const float*)d_in[7];
    const float* Ua1    = (const float*)d_in[8];
    const float* ba1    = (const float*)d_in[9];
    const float* Wa2    = (const float*)d_in[10];
    const float* ba2    = (const float*)d_in[11];
    const float* gammas = (const float*)d_in[12];
    const float* betas  = (const float*)d_in[13];
    float* out = (float*)d_out;

    pack_k<<<(256 * XPW + 255) / 256, 256>>>(W, Wa1, 0);
    pack_k<<<(256 * XPW + 255) / 256, 256>>>(U, Ua1, 1);
    initmask_k<<<NROWS / 256, 256>>>(maskp);

    // embedding: g_hseq = permute(x) @ W_emb + b_emb
    gemm_k<<<dim3(2, 256), 256>>>(x, W_emb, b_emb, 256, 0);

    for (int d = 0; d < NDEPTH; d++) {
        gemm_k<<<dim3(7, 256), 256>>>(nullptr, nullptr, nullptr, XPW, 1);
        lnx_k<<<NROWS, 256>>>(gammas, betas);
        scan_k<<<128, 512>>>(b, ba1, Wa2, ba2,
                             gammas + H3, betas + H3,
                             out, out_size, d, d & 1);
    }

    copyout_k<<<64, 256>>>(out, out_size);
}